// round 11
// baseline (speedup 1.0000x reference)
#include <cuda_runtime.h>
#include <cuda_bf16.h>
#include <math.h>
#include <stdint.h>

#define BB 8192
#define DD 64
#define NT 64          // 128-row tiles
#define NTRI 2080      // NT*(NT+1)/2
#define NTILES (2 * NTRI)
#define GRID_GEMM 296  // 2 CTAs x 148 SMs, persistent
#define TILE_BYTES 16384
#define BUF_BYTES 32768
#define NSTAGE 3
#define STAGGER_CYC 3000   // ~half a tile: anti-phase the second CTA per SM

// ---------------- scratch (no allocations allowed) ----------------
__device__ float g_rstd[2][DD];
__device__ float g_vpart[2 * 2 * 64 * 64];   // [pair][s1|s2][chunk][d]
__device__ unsigned int g_ticket;            // work-stealing counter (reset in varB)
// Y stored PRE-SWIZZLED (SW128) per 128-row tile.
__device__ unsigned char g_Yb[2][BB * 128];
// TRANSPOSED partials: [slot][pair*BB + row] -> coalesced STG and LDG.
__device__ float g_part[NT][2 * BB];

// ---------------- helpers ----------------
__device__ __forceinline__ uint32_t smem_u32(const void* p) {
    uint32_t a;
    asm("{ .reg .u64 t; cvta.to.shared.u64 t, %1; cvt.u32.u64 %0, t; }" : "=r"(a) : "l"(p));
    return a;
}

__device__ __forceinline__ void ldsm_x4(uint32_t* r, uint32_t addr) {
    asm volatile("ldmatrix.sync.aligned.m8n8.x4.shared.b16 {%0,%1,%2,%3}, [%4];"
                 : "=r"(r[0]), "=r"(r[1]), "=r"(r[2]), "=r"(r[3]) : "r"(addr));
}

__device__ __forceinline__ void mma16816(float* d, const uint32_t* a, const uint32_t* b) {
    asm volatile(
        "mma.sync.aligned.m16n8k16.row.col.f32.bf16.bf16.f32 "
        "{%0,%1,%2,%3}, {%4,%5,%6,%7}, {%8,%9}, {%0,%1,%2,%3};"
        : "+f"(d[0]), "+f"(d[1]), "+f"(d[2]), "+f"(d[3])
        : "r"(a[0]), "r"(a[1]), "r"(a[2]), "r"(a[3]), "r"(b[0]), "r"(b[1]));
}

__device__ __forceinline__ float msqrt(float q) {
    float sv;
    asm("sqrt.approx.f32 %0, %1;" : "=f"(sv) : "f"(fmaxf(q, 0.0f)));
    return sv;
}

#define MBAR_INIT(addr, cnt) \
    asm volatile("mbarrier.init.shared.b64 [%0], %1;" :: "r"(addr), "r"(cnt) : "memory")
#define MBAR_EXPECT_TX(addr, bytes) \
    asm volatile("mbarrier.arrive.expect_tx.shared.b64 _, [%0], %1;" :: "r"(addr), "r"(bytes) : "memory")
#define MBAR_WAIT(addr, parity) do {                                              \
    uint32_t _m = (addr); uint32_t _p = (parity); uint32_t _done;                 \
    asm volatile("{ .reg .pred p;\n\t"                                            \
        "mbarrier.try_wait.parity.acquire.cta.shared::cta.b64 p, [%1], %2;\n\t"   \
        "selp.b32 %0, 1, 0, p; }" : "=r"(_done) : "r"(_m), "r"(_p) : "memory");   \
    if (!_done) {                                                                 \
        asm volatile("{ .reg .pred P1;\n\t"                                       \
        "WL_%=:\n\t"                                                              \
        "mbarrier.try_wait.parity.acquire.cta.shared::cta.b64 P1, [%0], %1, 0x989680;\n\t" \
        "@P1 bra.uni WD_%=;\n\t"                                                  \
        "bra.uni WL_%=;\n\t"                                                      \
        "WD_%=: }" :: "r"(_m), "r"(_p) : "memory");                               \
    }                                                                             \
} while (0)

__device__ __forceinline__ void bulk_copy(uint32_t dst_smem, const void* src, uint32_t bytes,
                                          uint32_t mbar) {
    asm volatile(
        "cp.async.bulk.shared::cluster.global.mbarrier::complete_tx::bytes [%0], [%1], %2, [%3];"
        :: "r"(dst_smem), "l"(src), "r"(bytes), "r"(mbar) : "memory");
}

__device__ __forceinline__ void tri_decode(int tt, int& ti, int& tj) {
    int j = (int)((sqrtf(8.0f * (float)tt + 1.0f) - 1.0f) * 0.5f);
    while ((j + 1) * (j + 2) / 2 <= tt) j++;
    while (j * (j + 1) / 2 > tt) j--;
    tj = j;
    ti = tt - j * (j + 1) / 2;
}

// ---------------------------------------------------------------------------
// Kernel 1a: coalesced per-block partial sums (s1, s2) per feature.
// ---------------------------------------------------------------------------
__global__ __launch_bounds__(256) void varA_kernel(const float* __restrict__ anchor,
                                                   const float* __restrict__ positive,
                                                   const float* __restrict__ negative) {
    int pair  = blockIdx.x >> 6;
    int chunk = blockIdx.x & 63;
    const float* bp = pair ? negative : positive;
    int t = threadIdx.x;
    int g = t & 15;
    int rr = t >> 4;

    float s1[4] = {0.f, 0.f, 0.f, 0.f};
    float s2[4] = {0.f, 0.f, 0.f, 0.f};
#pragma unroll
    for (int p = 0; p < 8; p++) {
        int r = chunk * 128 + p * 16 + rr;
        float4 a = reinterpret_cast<const float4*>(anchor)[r * 16 + g];
        float4 b = reinterpret_cast<const float4*>(bp)[r * 16 + g];
        float x, y;
        x = a.x + 1e-4f; y = b.x + 1e-4f; s1[0] += x + y; s2[0] += x * x + y * y;
        x = a.y + 1e-4f; y = b.y + 1e-4f; s1[1] += x + y; s2[1] += x * x + y * y;
        x = a.z + 1e-4f; y = b.z + 1e-4f; s1[2] += x + y; s2[2] += x * x + y * y;
        x = a.w + 1e-4f; y = b.w + 1e-4f; s1[3] += x + y; s2[3] += x * x + y * y;
    }
    __shared__ float sh[256 * 8];
#pragma unroll
    for (int c = 0; c < 4; c++) {
        sh[t * 8 + c]     = s1[c];
        sh[t * 8 + 4 + c] = s2[c];
    }
    __syncthreads();
    if (t < 128) {
        int d  = t & 63;
        int wh = t >> 6;        // 0: s1, 1: s2
        int gg = d >> 2, c = d & 3;
        float s = 0.f;
#pragma unroll
        for (int k = 0; k < 16; k++)
            s += sh[(gg + 16 * k) * 8 + wh * 4 + c];
        g_vpart[((pair * 2 + wh) * 64 + chunk) * 64 + d] = s;
    }
}

// ---------------------------------------------------------------------------
// Kernel 1b: finish variance -> rstd; reset work-stealing ticket.
// ---------------------------------------------------------------------------
__global__ void varB_kernel() {
    int t = threadIdx.x;        // 0..127
    if (t == 0) g_ticket = 0;
    int pair = t >> 6, d = t & 63;
    float s1 = 0.f, s2 = 0.f;
#pragma unroll 8
    for (int chunk = 0; chunk < 64; chunk++) {
        s1 += g_vpart[((pair * 2 + 0) * 64 + chunk) * 64 + d];
        s2 += g_vpart[((pair * 2 + 1) * 64 + chunk) * 64 + d];
    }
    const float n = 2.0f * BB;
    float mean = s1 / n;
    float var  = s2 / n - mean * mean;
    g_rstd[pair][d] = 1.0f / sqrtf(var);
}

// ---------------------------------------------------------------------------
// Kernel 2: Y = (a-b)*rstd (bf16), written PRE-SWIZZLED per 128-row tile.
// ---------------------------------------------------------------------------
__global__ void build_kernel(const float* __restrict__ anchor,
                             const float* __restrict__ positive,
                             const float* __restrict__ negative) {
    int idx = blockIdx.x * blockDim.x + threadIdx.x;  // 0 .. 2*8192*16-1
    int pair = idx >> 17;
    int rem  = idx & 131071;
    int r = rem >> 4;
    int g = rem & 15;          // 4-feature group (8 output bytes)
    const float* bp = pair ? negative : positive;
    float4 av = reinterpret_cast<const float4*>(anchor)[r * 16 + g];
    float4 bv = reinterpret_cast<const float4*>(bp)[r * 16 + g];
    float4 rs = reinterpret_cast<const float4*>(g_rstd[pair])[g];
    __nv_bfloat162 lo = __floats2bfloat162_rn((av.x - bv.x) * rs.x, (av.y - bv.y) * rs.y);
    __nv_bfloat162 hi = __floats2bfloat162_rn((av.z - bv.z) * rs.z, (av.w - bv.w) * rs.w);
    uint2 pk;
    *reinterpret_cast<__nv_bfloat162*>(&pk.x) = lo;
    *reinterpret_cast<__nv_bfloat162*>(&pk.y) = hi;
    int tile = r >> 7, lr = r & 127;
    uint32_t off = (uint32_t)lr * 128 + g * 8;
    uint32_t sw = off ^ ((off >> 3) & 0x70);
    *reinterpret_cast<uint2*>(&g_Yb[pair][tile * TILE_BYTES + sw]) = pk;
}

// ---------------------------------------------------------------------------
// Kernel 3: persistent triangular GEMM, 3-stage cp.async.bulk pipeline,
// work-stealing scheduler, ANTI-PHASE STAGGER between the two CTAs per SM.
// ---------------------------------------------------------------------------
__global__ __launch_bounds__(256, 2) void gemm_kernel() {
    extern __shared__ char smem[];                 // NSTAGE x 32KB tile buffers
    __shared__ float srow2[2][512];
    __shared__ float scol2[2][256];
    __shared__ int pending[NSTAGE];
    __shared__ __align__(8) uint64_t mbar_full[NSTAGE];

    uint32_t smem_base = smem_u32(smem);
    uint32_t mbar0 = smem_u32(&mbar_full[0]);
    int tid = threadIdx.x;
    int lane = tid & 31;
    int wid = tid >> 5;
    int wr = wid >> 2;    // warp row (0,1) -> rows wr*64
    int wc = wid & 3;     // warp col (0..3) -> cols wc*32

    if (tid == 0) {
#pragma unroll
        for (int s = 0; s < NSTAGE; s++) MBAR_INIT(mbar0 + 8 * s, 1);
    }
    __syncthreads();

    // Prologue: grab NSTAGE tickets, issue their copies (loads fly during the
    // stagger spin below).
    if (tid == 0) {
#pragma unroll
        for (int s = 0; s < NSTAGE; s++) {
            int idx = (int)atomicAdd(&g_ticket, 1u);
            pending[s] = idx;
            if (idx < NTILES) {
                int pair = idx >= NTRI;
                int ti, tj;
                tri_decode(idx - pair * NTRI, ti, tj);
                uint32_t dst = smem_base + s * BUF_BYTES;
                MBAR_EXPECT_TX(mbar0 + 8 * s, BUF_BYTES);
                bulk_copy(dst, g_Yb[pair] + ti * TILE_BYTES, TILE_BYTES, mbar0 + 8 * s);
                bulk_copy(dst + TILE_BYTES, g_Yb[pair] + tj * TILE_BYTES, TILE_BYTES, mbar0 + 8 * s);
            }
        }
    }
    __syncthreads();

    // Anti-phase stagger: second CTA on each SM delays ~half a tile so its
    // tensor (mainloop) burst overlaps the other CTA's MUFU (epilogue) burst.
    if (blockIdx.x >= 148) {
        long long s0 = clock64();
        while (clock64() - s0 < STAGGER_CYC) { }
    }

    int a_row = lane & 15;                       // + wr*64 + mt*16
    int a_kb  = (lane >> 4) * 16;                // + kk*32
    int b_row = (lane & 7) + ((lane >> 4) << 3); // + wc*32 + ng*16
    int b_kb  = ((lane >> 3) & 1) * 16;          // + kk*32

    int n = 0, buf = 0;
    while (true) {
        int idx = pending[buf];   // written >=1 __syncthreads ago
        if (idx >= NTILES) break;
        uint32_t base = smem_base + buf * BUF_BYTES;

        int pair = idx >= NTRI;
        int ti, tj;
        tri_decode(idx - pair * NTRI, ti, tj);

        MBAR_WAIT(mbar0 + 8 * buf, (n / NSTAGE) & 1);

        // ---- mainloop: 4 k16 steps, warp tile 64x32 ----
        float acc[4][4][4];
#pragma unroll
        for (int mt = 0; mt < 4; mt++)
#pragma unroll
            for (int nt = 0; nt < 4; nt++)
#pragma unroll
                for (int f = 0; f < 4; f++) acc[mt][nt][f] = 0.f;

#pragma unroll
        for (int kk = 0; kk < 4; kk++) {
            uint32_t af[4][4];
#pragma unroll
            for (int mt = 0; mt < 4; mt++) {
                int row = wr * 64 + mt * 16 + a_row;
                int kb = kk * 32 + a_kb;
                uint32_t addr = base + row * 128 + (kb ^ ((row & 7) * 16));
                ldsm_x4(af[mt], addr);
            }
            uint32_t bfr[2][4];
#pragma unroll
            for (int ng = 0; ng < 2; ng++) {
                int row = wc * 32 + ng * 16 + b_row;
                int kb = kk * 32 + b_kb;
                uint32_t addr = base + TILE_BYTES + row * 128 + (kb ^ ((row & 7) * 16));
                ldsm_x4(bfr[ng], addr);
            }
#pragma unroll
            for (int mt = 0; mt < 4; mt++)
#pragma unroll
                for (int nt = 0; nt < 4; nt++)
                    mma16816(acc[mt][nt], af[mt], &bfr[nt >> 1][(nt & 1) * 2]);
        }

        // ---- fused epilogue: sqrt + row/col partials ----
        float rs[4][2], cs[4][2];
#pragma unroll
        for (int mt = 0; mt < 4; mt++) { rs[mt][0] = 0.f; rs[mt][1] = 0.f; }
#pragma unroll
        for (int nt = 0; nt < 4; nt++) { cs[nt][0] = 0.f; cs[nt][1] = 0.f; }
#pragma unroll
        for (int mt = 0; mt < 4; mt++)
#pragma unroll
            for (int nt = 0; nt < 4; nt++) {
                float s0 = msqrt(acc[mt][nt][0]);
                float s1 = msqrt(acc[mt][nt][1]);
                float s2 = msqrt(acc[mt][nt][2]);
                float s3 = msqrt(acc[mt][nt][3]);
                rs[mt][0] += s0 + s1;
                rs[mt][1] += s2 + s3;
                cs[nt][0] += s0 + s2;
                cs[nt][1] += s1 + s3;
            }

#pragma unroll
        for (int o = 1; o <= 2; o <<= 1)
#pragma unroll
            for (int mt = 0; mt < 4; mt++) {
                rs[mt][0] += __shfl_xor_sync(0xffffffffu, rs[mt][0], o);
                rs[mt][1] += __shfl_xor_sync(0xffffffffu, rs[mt][1], o);
            }
#pragma unroll
        for (int o = 4; o <= 16; o <<= 1)
#pragma unroll
            for (int nt = 0; nt < 4; nt++) {
                cs[nt][0] += __shfl_xor_sync(0xffffffffu, cs[nt][0], o);
                cs[nt][1] += __shfl_xor_sync(0xffffffffu, cs[nt][1], o);
            }

        float* srow = srow2[n & 1];
        float* scol = scol2[n & 1];
        if ((lane & 3) == 0) {
            int g = lane >> 2;  // 0..7
#pragma unroll
            for (int mt = 0; mt < 4; mt++) {
                srow[(wr * 64 + mt * 16 + g) * 4 + wc]     = rs[mt][0];
                srow[(wr * 64 + mt * 16 + g + 8) * 4 + wc] = rs[mt][1];
            }
        }
        if (lane < 4) {
#pragma unroll
            for (int nt = 0; nt < 4; nt++) {
                scol[(wc * 32 + nt * 8 + lane * 2) * 2 + wr]     = cs[nt][0];
                scol[(wc * 32 + nt * 8 + lane * 2 + 1) * 2 + wr] = cs[nt][1];
            }
        }
        __syncthreads();   // all mainloop reads of `buf` complete past this point

        // Producer: grab next ticket, refill this buffer.
        if (tid == 0) {
            int idx2 = (int)atomicAdd(&g_ticket, 1u);
            pending[buf] = idx2;
            if (idx2 < NTILES) {
                int pair2 = idx2 >= NTRI;
                int ti2, tj2;
                tri_decode(idx2 - pair2 * NTRI, ti2, tj2);
                uint32_t dst = smem_base + buf * BUF_BYTES;
                MBAR_EXPECT_TX(mbar0 + 8 * buf, BUF_BYTES);
                bulk_copy(dst, g_Yb[pair2] + ti2 * TILE_BYTES, TILE_BYTES, mbar0 + 8 * buf);
                bulk_copy(dst + TILE_BYTES, g_Yb[pair2] + tj2 * TILE_BYTES, TILE_BYTES, mbar0 + 8 * buf);
            }
        }

        // Coalesced partial writes: g_part[slot][pair*BB + row]
        if (tid < 128) {
            const float4 v = reinterpret_cast<const float4*>(srow)[tid];
            g_part[tj][pair * BB + ti * 128 + tid] = (v.x + v.y) + (v.z + v.w);
        } else if (ti != tj) {
            int c = tid - 128;
            g_part[ti][pair * BB + tj * 128 + c] = scol[c * 2] + scol[c * 2 + 1];
        }

        n++;
        buf++;
        if (buf == NSTAGE) buf = 0;
    }
}

// ---------------------------------------------------------------------------
// Kernel 4: reduce 64 slots per row; 4 threads/row (each sums 16 coalesced
// slots with 4-way ILP) + shuffle combine.
// ---------------------------------------------------------------------------
__global__ __launch_bounds__(256) void reduce_kernel(float* __restrict__ out) {
    int idx = blockIdx.x * blockDim.x + threadIdx.x;  // 0..65535
    int row = idx >> 2, q = idx & 3;
    float s0 = 0.f, s1 = 0.f, s2 = 0.f, s3 = 0.f;
    int j0 = q * 16;
#pragma unroll
    for (int j = 0; j < 16; j += 4) {
        s0 += g_part[j0 + j + 0][row];
        s1 += g_part[j0 + j + 1][row];
        s2 += g_part[j0 + j + 2][row];
        s3 += g_part[j0 + j + 3][row];
    }
    float s = (s0 + s1) + (s2 + s3);
    s += __shfl_xor_sync(0xffffffffu, s, 1);
    s += __shfl_xor_sync(0xffffffffu, s, 2);
    if (q == 0) out[row] = s + 8192.0f * 1e-6f;
}

extern "C" void kernel_launch(void* const* d_in, const int* in_sizes, int n_in,
                              void* d_out, int out_size) {
    (void)in_sizes; (void)n_in; (void)out_size;
    const float* anchor   = (const float*)d_in[0];
    const float* positive = (const float*)d_in[1];
    const float* negative = (const float*)d_in[2];
    float* out = (float*)d_out;

    varA_kernel<<<128, 256>>>(anchor, positive, negative);
    varB_kernel<<<1, 128>>>();
    build_kernel<<<1024, 256>>>(anchor, positive, negative);
    cudaFuncSetAttribute(gemm_kernel, cudaFuncAttributeMaxDynamicSharedMemorySize,
                         NSTAGE * BUF_BYTES);
    gemm_kernel<<<GRID_GEMM, 256, NSTAGE * BUF_BYTES>>>();
    reduce_kernel<<<256, 256>>>(out);
}

// round 12
// speedup vs baseline: 1.0687x; 1.0687x over previous
#include <cuda_runtime.h>
#include <cuda_bf16.h>
#include <math.h>
#include <stdint.h>

#define BB 8192
#define DD 64
#define NT 64          // 128-row tiles
#define NTRI 2080      // NT*(NT+1)/2
#define NTILES (2 * NTRI)
#define GRID_GEMM 296  // 2 CTAs x 148 SMs, persistent
#define TILE_BYTES 16384
#define BUF_BYTES 32768
#define NSTAGE 3
#define GRID_PREP 128  // must be <= SM count: grid-wide spin barrier

// ---------------- scratch (no allocations allowed) ----------------
__device__ float g_vpart[2 * 2 * 64 * 64];   // [pair][s1|s2][chunk][d]
__device__ unsigned int g_ticket;            // gemm work-stealing (reset in prep)
__device__ unsigned int g_done;              // prep grid barrier (reset in reduce)
// Y stored PRE-SWIZZLED (SW128) per 128-row tile.
__device__ unsigned char g_Yb[2][BB * 128];
// TRANSPOSED partials: [slot][pair*BB + row] -> coalesced STG and LDG.
__device__ float g_part[NT][2 * BB];

// ---------------- helpers ----------------
__device__ __forceinline__ uint32_t smem_u32(const void* p) {
    uint32_t a;
    asm("{ .reg .u64 t; cvta.to.shared.u64 t, %1; cvt.u32.u64 %0, t; }" : "=r"(a) : "l"(p));
    return a;
}

__device__ __forceinline__ void ldsm_x4(uint32_t* r, uint32_t addr) {
    asm volatile("ldmatrix.sync.aligned.m8n8.x4.shared.b16 {%0,%1,%2,%3}, [%4];"
                 : "=r"(r[0]), "=r"(r[1]), "=r"(r[2]), "=r"(r[3]) : "r"(addr));
}

__device__ __forceinline__ void mma16816(float* d, const uint32_t* a, const uint32_t* b) {
    asm volatile(
        "mma.sync.aligned.m16n8k16.row.col.f32.bf16.bf16.f32 "
        "{%0,%1,%2,%3}, {%4,%5,%6,%7}, {%8,%9}, {%0,%1,%2,%3};"
        : "+f"(d[0]), "+f"(d[1]), "+f"(d[2]), "+f"(d[3])
        : "r"(a[0]), "r"(a[1]), "r"(a[2]), "r"(a[3]), "r"(b[0]), "r"(b[1]));
}

__device__ __forceinline__ float msqrt(float q) {
    float sv;
    asm("sqrt.approx.f32 %0, %1;" : "=f"(sv) : "f"(fmaxf(q, 0.0f)));
    return sv;
}

#define MBAR_INIT(addr, cnt) \
    asm volatile("mbarrier.init.shared.b64 [%0], %1;" :: "r"(addr), "r"(cnt) : "memory")
#define MBAR_EXPECT_TX(addr, bytes) \
    asm volatile("mbarrier.arrive.expect_tx.shared.b64 _, [%0], %1;" :: "r"(addr), "r"(bytes) : "memory")
#define MBAR_WAIT(addr, parity) do {                                              \
    uint32_t _m = (addr); uint32_t _p = (parity); uint32_t _done;                 \
    asm volatile("{ .reg .pred p;\n\t"                                            \
        "mbarrier.try_wait.parity.acquire.cta.shared::cta.b64 p, [%1], %2;\n\t"   \
        "selp.b32 %0, 1, 0, p; }" : "=r"(_done) : "r"(_m), "r"(_p) : "memory");   \
    if (!_done) {                                                                 \
        asm volatile("{ .reg .pred P1;\n\t"                                       \
        "WL_%=:\n\t"                                                              \
        "mbarrier.try_wait.parity.acquire.cta.shared::cta.b64 P1, [%0], %1, 0x989680;\n\t" \
        "@P1 bra.uni WD_%=;\n\t"                                                  \
        "bra.uni WL_%=;\n\t"                                                      \
        "WD_%=: }" :: "r"(_m), "r"(_p) : "memory");                               \
    }                                                                             \
} while (0)

__device__ __forceinline__ void bulk_copy(uint32_t dst_smem, const void* src, uint32_t bytes,
                                          uint32_t mbar) {
    asm volatile(
        "cp.async.bulk.shared::cluster.global.mbarrier::complete_tx::bytes [%0], [%1], %2, [%3];"
        :: "r"(dst_smem), "l"(src), "r"(bytes), "r"(mbar) : "memory");
}

__device__ __forceinline__ void tri_decode(int tt, int& ti, int& tj) {
    int j = (int)((sqrtf(8.0f * (float)tt + 1.0f) - 1.0f) * 0.5f);
    while ((j + 1) * (j + 2) / 2 <= tt) j++;
    while (j * (j + 1) / 2 > tt) j--;
    tj = j;
    ti = tt - j * (j + 1) / 2;
}

// ---------------------------------------------------------------------------
// Kernel 1: FUSED variance + rstd + build. 128 CTAs (all resident on 148 SMs)
// with a software grid barrier between the variance partials and the build.
// Deterministic: identical arithmetic to the previous 3-kernel version.
// ---------------------------------------------------------------------------
__global__ __launch_bounds__(256) void prep_kernel(const float* __restrict__ anchor,
                                                   const float* __restrict__ positive,
                                                   const float* __restrict__ negative) {
    __shared__ float sh[256 * 8];
    __shared__ float sh_rstd[2][DD];
    int cta = blockIdx.x;          // 0..127
    int pair  = cta >> 6;
    int chunk = cta & 63;
    const float* bp0 = pair ? negative : positive;
    int t = threadIdx.x;

    // -------- phase 1: per-(pair,chunk) partial sums (as old varA) --------
    {
        int g = t & 15;
        int rr = t >> 4;
        float s1[4] = {0.f, 0.f, 0.f, 0.f};
        float s2[4] = {0.f, 0.f, 0.f, 0.f};
#pragma unroll
        for (int p = 0; p < 8; p++) {
            int r = chunk * 128 + p * 16 + rr;
            float4 a = reinterpret_cast<const float4*>(anchor)[r * 16 + g];
            float4 b = reinterpret_cast<const float4*>(bp0)[r * 16 + g];
            float x, y;
            x = a.x + 1e-4f; y = b.x + 1e-4f; s1[0] += x + y; s2[0] += x * x + y * y;
            x = a.y + 1e-4f; y = b.y + 1e-4f; s1[1] += x + y; s2[1] += x * x + y * y;
            x = a.z + 1e-4f; y = b.z + 1e-4f; s1[2] += x + y; s2[2] += x * x + y * y;
            x = a.w + 1e-4f; y = b.w + 1e-4f; s1[3] += x + y; s2[3] += x * x + y * y;
        }
#pragma unroll
        for (int c = 0; c < 4; c++) {
            sh[t * 8 + c]     = s1[c];
            sh[t * 8 + 4 + c] = s2[c];
        }
        __syncthreads();
        if (t < 128) {
            int d  = t & 63;
            int wh = t >> 6;        // 0: s1, 1: s2
            int gg = d >> 2, c = d & 3;
            float s = 0.f;
#pragma unroll
            for (int k = 0; k < 16; k++)
                s += sh[(gg + 16 * k) * 8 + wh * 4 + c];
            g_vpart[((pair * 2 + wh) * 64 + chunk) * 64 + d] = s;
        }
        if (t == 0 && cta == 0) g_ticket = 0;   // reset gemm scheduler
    }
    __syncthreads();

    // -------- grid barrier (all 128 CTAs resident -> spin is safe) --------
    if (t == 0) {
        __threadfence();
        atomicAdd(&g_done, 1u);
        while (atomicAdd(&g_done, 0u) < GRID_PREP) { }
    }
    __syncthreads();

    // -------- phase 2: every CTA computes rstd into smem (as old varB) ----
    if (t < 128) {
        int pr = t >> 6, d = t & 63;
        float s1 = 0.f, s2 = 0.f;
#pragma unroll 8
        for (int ch = 0; ch < 64; ch++) {
            s1 += g_vpart[((pr * 2 + 0) * 64 + ch) * 64 + d];
            s2 += g_vpart[((pr * 2 + 1) * 64 + ch) * 64 + d];
        }
        const float nn = 2.0f * BB;
        float mean = s1 / nn;
        float var  = s2 / nn - mean * mean;
        sh_rstd[pr][d] = 1.0f / sqrtf(var);
    }
    __syncthreads();

    // -------- phase 3: build Y (pre-swizzled bf16), 64 rows/pair per CTA --
#pragma unroll
    for (int pr = 0; pr < 2; pr++) {
        const float* bp = pr ? negative : positive;
#pragma unroll
        for (int it = 0; it < 4; it++) {
            int local = it * 256 + t;          // 0..1023
            int r = cta * 64 + (local >> 4);
            int g = local & 15;
            float4 av = reinterpret_cast<const float4*>(anchor)[r * 16 + g];
            float4 bv = reinterpret_cast<const float4*>(bp)[r * 16 + g];
            float4 rs = reinterpret_cast<const float4*>(sh_rstd[pr])[g];
            __nv_bfloat162 lo = __floats2bfloat162_rn((av.x - bv.x) * rs.x, (av.y - bv.y) * rs.y);
            __nv_bfloat162 hi = __floats2bfloat162_rn((av.z - bv.z) * rs.z, (av.w - bv.w) * rs.w);
            uint2 pk;
            *reinterpret_cast<__nv_bfloat162*>(&pk.x) = lo;
            *reinterpret_cast<__nv_bfloat162*>(&pk.y) = hi;
            int tile = r >> 7, lr = r & 127;
            uint32_t off = (uint32_t)lr * 128 + g * 8;
            uint32_t sw = off ^ ((off >> 3) & 0x70);
            *reinterpret_cast<uint2*>(&g_Yb[pr][tile * TILE_BYTES + sw]) = pk;
        }
    }
}

// ---------------------------------------------------------------------------
// Kernel 2: persistent triangular GEMM, 3-stage cp.async.bulk pipeline,
// work-stealing scheduler.
// ---------------------------------------------------------------------------
__global__ __launch_bounds__(256, 2) void gemm_kernel() {
    extern __shared__ char smem[];                 // NSTAGE x 32KB tile buffers
    __shared__ float srow2[2][512];
    __shared__ float scol2[2][256];
    __shared__ int pending[NSTAGE];
    __shared__ __align__(8) uint64_t mbar_full[NSTAGE];

    uint32_t smem_base = smem_u32(smem);
    uint32_t mbar0 = smem_u32(&mbar_full[0]);
    int tid = threadIdx.x;
    int lane = tid & 31;
    int wid = tid >> 5;
    int wr = wid >> 2;    // warp row (0,1) -> rows wr*64
    int wc = wid & 3;     // warp col (0..3) -> cols wc*32

    if (tid == 0) {
#pragma unroll
        for (int s = 0; s < NSTAGE; s++) MBAR_INIT(mbar0 + 8 * s, 1);
    }
    __syncthreads();

    // Prologue: grab NSTAGE tickets, issue their copies.
    if (tid == 0) {
#pragma unroll
        for (int s = 0; s < NSTAGE; s++) {
            int idx = (int)atomicAdd(&g_ticket, 1u);
            pending[s] = idx;
            if (idx < NTILES) {
                int pair = idx >= NTRI;
                int ti, tj;
                tri_decode(idx - pair * NTRI, ti, tj);
                uint32_t dst = smem_base + s * BUF_BYTES;
                MBAR_EXPECT_TX(mbar0 + 8 * s, BUF_BYTES);
                bulk_copy(dst, g_Yb[pair] + ti * TILE_BYTES, TILE_BYTES, mbar0 + 8 * s);
                bulk_copy(dst + TILE_BYTES, g_Yb[pair] + tj * TILE_BYTES, TILE_BYTES, mbar0 + 8 * s);
            }
        }
    }
    __syncthreads();

    int a_row = lane & 15;                       // + wr*64 + mt*16
    int a_kb  = (lane >> 4) * 16;                // + kk*32
    int b_row = (lane & 7) + ((lane >> 4) << 3); // + wc*32 + ng*16
    int b_kb  = ((lane >> 3) & 1) * 16;          // + kk*32

    int n = 0, buf = 0;
    while (true) {
        int idx = pending[buf];   // written >=1 __syncthreads ago
        if (idx >= NTILES) break;
        uint32_t base = smem_base + buf * BUF_BYTES;

        int pair = idx >= NTRI;
        int ti, tj;
        tri_decode(idx - pair * NTRI, ti, tj);

        MBAR_WAIT(mbar0 + 8 * buf, (n / NSTAGE) & 1);

        // ---- mainloop: 4 k16 steps, warp tile 64x32 ----
        float acc[4][4][4];
#pragma unroll
        for (int mt = 0; mt < 4; mt++)
#pragma unroll
            for (int nt = 0; nt < 4; nt++)
#pragma unroll
                for (int f = 0; f < 4; f++) acc[mt][nt][f] = 0.f;

#pragma unroll
        for (int kk = 0; kk < 4; kk++) {
            uint32_t af[4][4];
#pragma unroll
            for (int mt = 0; mt < 4; mt++) {
                int row = wr * 64 + mt * 16 + a_row;
                int kb = kk * 32 + a_kb;
                uint32_t addr = base + row * 128 + (kb ^ ((row & 7) * 16));
                ldsm_x4(af[mt], addr);
            }
            uint32_t bfr[2][4];
#pragma unroll
            for (int ng = 0; ng < 2; ng++) {
                int row = wc * 32 + ng * 16 + b_row;
                int kb = kk * 32 + b_kb;
                uint32_t addr = base + TILE_BYTES + row * 128 + (kb ^ ((row & 7) * 16));
                ldsm_x4(bfr[ng], addr);
            }
#pragma unroll
            for (int mt = 0; mt < 4; mt++)
#pragma unroll
                for (int nt = 0; nt < 4; nt++)
                    mma16816(acc[mt][nt], af[mt], &bfr[nt >> 1][(nt & 1) * 2]);
        }

        // ---- fused epilogue: sqrt + row/col partials ----
        float rs[4][2], cs[4][2];
#pragma unroll
        for (int mt = 0; mt < 4; mt++) { rs[mt][0] = 0.f; rs[mt][1] = 0.f; }
#pragma unroll
        for (int nt = 0; nt < 4; nt++) { cs[nt][0] = 0.f; cs[nt][1] = 0.f; }
#pragma unroll
        for (int mt = 0; mt < 4; mt++)
#pragma unroll
            for (int nt = 0; nt < 4; nt++) {
                float s0 = msqrt(acc[mt][nt][0]);
                float s1 = msqrt(acc[mt][nt][1]);
                float s2 = msqrt(acc[mt][nt][2]);
                float s3 = msqrt(acc[mt][nt][3]);
                rs[mt][0] += s0 + s1;
                rs[mt][1] += s2 + s3;
                cs[nt][0] += s0 + s2;
                cs[nt][1] += s1 + s3;
            }

#pragma unroll
        for (int o = 1; o <= 2; o <<= 1)
#pragma unroll
            for (int mt = 0; mt < 4; mt++) {
                rs[mt][0] += __shfl_xor_sync(0xffffffffu, rs[mt][0], o);
                rs[mt][1] += __shfl_xor_sync(0xffffffffu, rs[mt][1], o);
            }
#pragma unroll
        for (int o = 4; o <= 16; o <<= 1)
#pragma unroll
            for (int nt = 0; nt < 4; nt++) {
                cs[nt][0] += __shfl_xor_sync(0xffffffffu, cs[nt][0], o);
                cs[nt][1] += __shfl_xor_sync(0xffffffffu, cs[nt][1], o);
            }

        float* srow = srow2[n & 1];
        float* scol = scol2[n & 1];
        if ((lane & 3) == 0) {
            int g = lane >> 2;  // 0..7
#pragma unroll
            for (int mt = 0; mt < 4; mt++) {
                srow[(wr * 64 + mt * 16 + g) * 4 + wc]     = rs[mt][0];
                srow[(wr * 64 + mt * 16 + g + 8) * 4 + wc] = rs[mt][1];
            }
        }
        if (lane < 4) {
#pragma unroll
            for (int nt = 0; nt < 4; nt++) {
                scol[(wc * 32 + nt * 8 + lane * 2) * 2 + wr]     = cs[nt][0];
                scol[(wc * 32 + nt * 8 + lane * 2 + 1) * 2 + wr] = cs[nt][1];
            }
        }
        __syncthreads();   // all mainloop reads of `buf` complete past this point

        // Producer: grab next ticket, refill this buffer.
        if (tid == 0) {
            int idx2 = (int)atomicAdd(&g_ticket, 1u);
            pending[buf] = idx2;
            if (idx2 < NTILES) {
                int pair2 = idx2 >= NTRI;
                int ti2, tj2;
                tri_decode(idx2 - pair2 * NTRI, ti2, tj2);
                uint32_t dst = smem_base + buf * BUF_BYTES;
                MBAR_EXPECT_TX(mbar0 + 8 * buf, BUF_BYTES);
                bulk_copy(dst, g_Yb[pair2] + ti2 * TILE_BYTES, TILE_BYTES, mbar0 + 8 * buf);
                bulk_copy(dst + TILE_BYTES, g_Yb[pair2] + tj2 * TILE_BYTES, TILE_BYTES, mbar0 + 8 * buf);
            }
        }

        // Coalesced partial writes: g_part[slot][pair*BB + row]
        if (tid < 128) {
            const float4 v = reinterpret_cast<const float4*>(srow)[tid];
            g_part[tj][pair * BB + ti * 128 + tid] = (v.x + v.y) + (v.z + v.w);
        } else if (ti != tj) {
            int c = tid - 128;
            g_part[ti][pair * BB + tj * 128 + c] = scol[c * 2] + scol[c * 2 + 1];
        }

        n++;
        buf++;
        if (buf == NSTAGE) buf = 0;
    }
}

// ---------------------------------------------------------------------------
// Kernel 3: reduce 64 slots per row; 4 threads/row + shuffle combine.
// Also resets the prep grid-barrier counter for the next graph replay.
// ---------------------------------------------------------------------------
__global__ __launch_bounds__(256) void reduce_kernel(float* __restrict__ out) {
    if (blockIdx.x == 0 && threadIdx.x == 0) g_done = 0;
    int idx = blockIdx.x * blockDim.x + threadIdx.x;  // 0..65535
    int row = idx >> 2, q = idx & 3;
    float s0 = 0.f, s1 = 0.f, s2 = 0.f, s3 = 0.f;
    int j0 = q * 16;
#pragma unroll
    for (int j = 0; j < 16; j += 4) {
        s0 += g_part[j0 + j + 0][row];
        s1 += g_part[j0 + j + 1][row];
        s2 += g_part[j0 + j + 2][row];
        s3 += g_part[j0 + j + 3][row];
    }
    float s = (s0 + s1) + (s2 + s3);
    s += __shfl_xor_sync(0xffffffffu, s, 1);
    s += __shfl_xor_sync(0xffffffffu, s, 2);
    if (q == 0) out[row] = s + 8192.0f * 1e-6f;
}

extern "C" void kernel_launch(void* const* d_in, const int* in_sizes, int n_in,
                              void* d_out, int out_size) {
    (void)in_sizes; (void)n_in; (void)out_size;
    const float* anchor   = (const float*)d_in[0];
    const float* positive = (const float*)d_in[1];
    const float* negative = (const float*)d_in[2];
    float* out = (float*)d_out;

    prep_kernel<<<GRID_PREP, 256>>>(anchor, positive, negative);
    cudaFuncSetAttribute(gemm_kernel, cudaFuncAttributeMaxDynamicSharedMemorySize,
                         NSTAGE * BUF_BYTES);
    gemm_kernel<<<GRID_GEMM, 256, NSTAGE * BUF_BYTES>>>();
    reduce_kernel<<<256, 256>>>(out);
}

// round 16
// speedup vs baseline: 1.0827x; 1.0131x over previous
#include <cuda_runtime.h>
#include <cuda_bf16.h>
#include <math.h>
#include <stdint.h>

#define BB 8192
#define DD 64
#define NT 64          // 128-row tiles
#define NTRI 2080      // NT*(NT+1)/2
#define NTILES (2 * NTRI)
#define GRID_GEMM 296  // 2 CTAs x 148 SMs, persistent
#define TILE_BYTES 16384
#define BUF_BYTES 32768
#define NSTAGE 3
#define GRID_PREP 128  // must be <= SM count: grid-wide spin barrier

// ---------------- scratch (no allocations allowed) ----------------
__device__ float g_vpart[2 * 2 * 64 * 64];   // [pair][s1|s2][chunk][d]
__device__ unsigned int g_ticket;            // gemm work-stealing (reset in prep)
__device__ unsigned int g_done;              // prep grid barrier (reset in reduce)
// Y stored PRE-SWIZZLED (SW128) per 128-row tile.
__device__ unsigned char g_Yb[2][BB * 128];
// TRANSPOSED partials: [slot][pair*BB + row] -> coalesced STG and LDG.
__device__ float g_part[NT][2 * BB];

// ---------------- helpers ----------------
__device__ __forceinline__ uint32_t smem_u32(const void* p) {
    uint32_t a;
    asm("{ .reg .u64 t; cvta.to.shared.u64 t, %1; cvt.u32.u64 %0, t; }" : "=r"(a) : "l"(p));
    return a;
}

__device__ __forceinline__ void ldsm_x4(uint32_t* r, uint32_t addr) {
    asm volatile("ldmatrix.sync.aligned.m8n8.x4.shared.b16 {%0,%1,%2,%3}, [%4];"
                 : "=r"(r[0]), "=r"(r[1]), "=r"(r[2]), "=r"(r[3]) : "r"(addr));
}

__device__ __forceinline__ void mma16816(float* d, const uint32_t* a, const uint32_t* b) {
    asm volatile(
        "mma.sync.aligned.m16n8k16.row.col.f32.bf16.bf16.f32 "
        "{%0,%1,%2,%3}, {%4,%5,%6,%7}, {%8,%9}, {%0,%1,%2,%3};"
        : "+f"(d[0]), "+f"(d[1]), "+f"(d[2]), "+f"(d[3])
        : "r"(a[0]), "r"(a[1]), "r"(a[2]), "r"(a[3]), "r"(b[0]), "r"(b[1]));
}

__device__ __forceinline__ float msqrt(float q) {
    float sv;
    asm("sqrt.approx.f32 %0, %1;" : "=f"(sv) : "f"(fmaxf(q, 0.0f)));
    return sv;
}

#define MBAR_INIT(addr, cnt) \
    asm volatile("mbarrier.init.shared.b64 [%0], %1;" :: "r"(addr), "r"(cnt) : "memory")
#define MBAR_EXPECT_TX(addr, bytes) \
    asm volatile("mbarrier.arrive.expect_tx.shared.b64 _, [%0], %1;" :: "r"(addr), "r"(bytes) : "memory")
#define MBAR_WAIT(addr, parity) do {                                              \
    uint32_t _m = (addr); uint32_t _p = (parity); uint32_t _done;                 \
    asm volatile("{ .reg .pred p;\n\t"                                            \
        "mbarrier.try_wait.parity.acquire.cta.shared::cta.b64 p, [%1], %2;\n\t"   \
        "selp.b32 %0, 1, 0, p; }" : "=r"(_done) : "r"(_m), "r"(_p) : "memory");   \
    if (!_done) {                                                                 \
        asm volatile("{ .reg .pred P1;\n\t"                                       \
        "WL_%=:\n\t"                                                              \
        "mbarrier.try_wait.parity.acquire.cta.shared::cta.b64 P1, [%0], %1, 0x989680;\n\t" \
        "@P1 bra.uni WD_%=;\n\t"                                                  \
        "bra.uni WL_%=;\n\t"                                                      \
        "WD_%=: }" :: "r"(_m), "r"(_p) : "memory");                               \
    }                                                                             \
} while (0)

__device__ __forceinline__ void bulk_copy(uint32_t dst_smem, const void* src, uint32_t bytes,
                                          uint32_t mbar) {
    asm volatile(
        "cp.async.bulk.shared::cluster.global.mbarrier::complete_tx::bytes [%0], [%1], %2, [%3];"
        :: "r"(dst_smem), "l"(src), "r"(bytes), "r"(mbar) : "memory");
}

__device__ __forceinline__ void tri_decode(int tt, int& ti, int& tj) {
    int j = (int)((sqrtf(8.0f * (float)tt + 1.0f) - 1.0f) * 0.5f);
    while ((j + 1) * (j + 2) / 2 <= tt) j++;
    while (j * (j + 1) / 2 > tt) j--;
    tj = j;
    ti = tt - j * (j + 1) / 2;
}

// ---------------------------------------------------------------------------
// Kernel 1: FUSED variance + rstd + build, with diff cached in smem.
// CTA = (pair, chunk): its 128 input rows ARE one output tile, so the diff
// computed during the variance pass is stashed in smem and phase 3 does
// ZERO global loads. Arithmetic identical to the unfused version.
// ---------------------------------------------------------------------------
__global__ __launch_bounds__(256) void prep_kernel(const float* __restrict__ anchor,
                                                   const float* __restrict__ positive,
                                                   const float* __restrict__ negative) {
    __shared__ float sh[256 * 8];        // 8 KB reduction buffer
    __shared__ float sdiff[128 * 64];    // 32 KB: diff tile, [lr][d]
    __shared__ float sh_rstd[2][DD];
    int cta = blockIdx.x;          // 0..127
    int pair  = cta >> 6;
    int chunk = cta & 63;
    const float* bp0 = pair ? negative : positive;
    int t = threadIdx.x;

    // -------- phase 1: variance partials + diff stash --------
    {
        int g = t & 15;
        int rr = t >> 4;
        float s1[4] = {0.f, 0.f, 0.f, 0.f};
        float s2[4] = {0.f, 0.f, 0.f, 0.f};
#pragma unroll
        for (int p = 0; p < 8; p++) {
            int lr = p * 16 + rr;
            int r = chunk * 128 + lr;
            float4 a = reinterpret_cast<const float4*>(anchor)[r * 16 + g];
            float4 b = reinterpret_cast<const float4*>(bp0)[r * 16 + g];
            float4 dv;
            dv.x = a.x - b.x; dv.y = a.y - b.y; dv.z = a.z - b.z; dv.w = a.w - b.w;
            *reinterpret_cast<float4*>(&sdiff[lr * 64 + g * 4]) = dv;
            float x, y;
            x = a.x + 1e-4f; y = b.x + 1e-4f; s1[0] += x + y; s2[0] += x * x + y * y;
            x = a.y + 1e-4f; y = b.y + 1e-4f; s1[1] += x + y; s2[1] += x * x + y * y;
            x = a.z + 1e-4f; y = b.z + 1e-4f; s1[2] += x + y; s2[2] += x * x + y * y;
            x = a.w + 1e-4f; y = b.w + 1e-4f; s1[3] += x + y; s2[3] += x * x + y * y;
        }
#pragma unroll
        for (int c = 0; c < 4; c++) {
            sh[t * 8 + c]     = s1[c];
            sh[t * 8 + 4 + c] = s2[c];
        }
        __syncthreads();
        if (t < 128) {
            int d  = t & 63;
            int wh = t >> 6;        // 0: s1, 1: s2
            int gg = d >> 2, c = d & 3;
            float s = 0.f;
#pragma unroll
            for (int k = 0; k < 16; k++)
                s += sh[(gg + 16 * k) * 8 + wh * 4 + c];
            g_vpart[((pair * 2 + wh) * 64 + chunk) * 64 + d] = s;
        }
        if (t == 0 && cta == 0) g_ticket = 0;   // reset gemm scheduler
    }
    __syncthreads();

    // -------- grid barrier (all 128 CTAs resident -> spin is safe) --------
    if (t == 0) {
        __threadfence();
        atomicAdd(&g_done, 1u);
        while (atomicAdd(&g_done, 0u) < GRID_PREP) { }
    }
    __syncthreads();

    // -------- phase 2: rstd into smem; chunk-sum split across 2 halves ----
    {
        int pr = (t >> 6) & 1;     // t:0..255 -> (pr, d, half)
        int d  = t & 63;
        int half = t >> 7;         // 0: chunks 0-31, 1: chunks 32-63
        float s1 = 0.f, s2 = 0.f;
#pragma unroll 8
        for (int ch = half * 32; ch < half * 32 + 32; ch++) {
            s1 += g_vpart[((pr * 2 + 0) * 64 + ch) * 64 + d];
            s2 += g_vpart[((pr * 2 + 1) * 64 + ch) * 64 + d];
        }
        sh[t] = s1;
        sh[256 + t] = s2;
        __syncthreads();
        if (t < 128) {
            float fs1 = sh[t] + sh[t + 128];
            float fs2 = sh[256 + t] + sh[256 + t + 128];
            const float nn = 2.0f * BB;
            float mean = fs1 / nn;
            float var  = fs2 / nn - mean * mean;
            sh_rstd[t >> 6][t & 63] = 1.0f / sqrtf(var);
        }
    }
    __syncthreads();

    // -------- phase 3: build this CTA's tile from smem (no global loads) --
#pragma unroll
    for (int it = 0; it < 8; it++) {
        int local = it * 256 + t;          // 0..2047
        int lr = local >> 4;
        int g = local & 15;
        float4 dv = *reinterpret_cast<const float4*>(&sdiff[lr * 64 + g * 4]);
        float4 rs = reinterpret_cast<const float4*>(sh_rstd[pair])[g];
        __nv_bfloat162 lo = __floats2bfloat162_rn(dv.x * rs.x, dv.y * rs.y);
        __nv_bfloat162 hi = __floats2bfloat162_rn(dv.z * rs.z, dv.w * rs.w);
        uint2 pk;
        *reinterpret_cast<__nv_bfloat162*>(&pk.x) = lo;
        *reinterpret_cast<__nv_bfloat162*>(&pk.y) = hi;
        uint32_t off = (uint32_t)lr * 128 + g * 8;
        uint32_t sw = off ^ ((off >> 3) & 0x70);
        *reinterpret_cast<uint2*>(&g_Yb[pair][chunk * TILE_BYTES + sw]) = pk;
    }
}

// ---------------------------------------------------------------------------
// Kernel 2: persistent triangular GEMM, 3-stage cp.async.bulk pipeline,
// work-stealing scheduler.
// ---------------------------------------------------------------------------
__global__ __launch_bounds__(256, 2) void gemm_kernel() {
    extern __shared__ char smem[];                 // NSTAGE x 32KB tile buffers
    __shared__ float srow2[2][512];
    __shared__ float scol2[2][256];
    __shared__ int pending[NSTAGE];
    __shared__ __align__(8) uint64_t mbar_full[NSTAGE];

    uint32_t smem_base = smem_u32(smem);
    uint32_t mbar0 = smem_u32(&mbar_full[0]);
    int tid = threadIdx.x;
    int lane = tid & 31;
    int wid = tid >> 5;
    int wr = wid >> 2;    // warp row (0,1) -> rows wr*64
    int wc = wid & 3;     // warp col (0..3) -> cols wc*32

    if (tid == 0) {
#pragma unroll
        for (int s = 0; s < NSTAGE; s++) MBAR_INIT(mbar0 + 8 * s, 1);
    }
    __syncthreads();

    // Prologue: grab NSTAGE tickets, issue their copies.
    if (tid == 0) {
#pragma unroll
        for (int s = 0; s < NSTAGE; s++) {
            int idx = (int)atomicAdd(&g_ticket, 1u);
            pending[s] = idx;
            if (idx < NTILES) {
                int pair = idx >= NTRI;
                int ti, tj;
                tri_decode(idx - pair * NTRI, ti, tj);
                uint32_t dst = smem_base + s * BUF_BYTES;
                MBAR_EXPECT_TX(mbar0 + 8 * s, BUF_BYTES);
                bulk_copy(dst, g_Yb[pair] + ti * TILE_BYTES, TILE_BYTES, mbar0 + 8 * s);
                bulk_copy(dst + TILE_BYTES, g_Yb[pair] + tj * TILE_BYTES, TILE_BYTES, mbar0 + 8 * s);
            }
        }
    }
    __syncthreads();

    int a_row = lane & 15;                       // + wr*64 + mt*16
    int a_kb  = (lane >> 4) * 16;                // + kk*32
    int b_row = (lane & 7) + ((lane >> 4) << 3); // + wc*32 + ng*16
    int b_kb  = ((lane >> 3) & 1) * 16;          // + kk*32

    int n = 0, buf = 0;
    while (true) {
        int idx = pending[buf];   // written >=1 __syncthreads ago
        if (idx >= NTILES) break;
        uint32_t base = smem_base + buf * BUF_BYTES;

        int pair = idx >= NTRI;
        int ti, tj;
        tri_decode(idx - pair * NTRI, ti, tj);

        MBAR_WAIT(mbar0 + 8 * buf, (n / NSTAGE) & 1);

        // ---- mainloop: 4 k16 steps, warp tile 64x32 ----
        float acc[4][4][4];
#pragma unroll
        for (int mt = 0; mt < 4; mt++)
#pragma unroll
            for (int nt = 0; nt < 4; nt++)
#pragma unroll
                for (int f = 0; f < 4; f++) acc[mt][nt][f] = 0.f;

#pragma unroll
        for (int kk = 0; kk < 4; kk++) {
            uint32_t af[4][4];
#pragma unroll
            for (int mt = 0; mt < 4; mt++) {
                int row = wr * 64 + mt * 16 + a_row;
                int kb = kk * 32 + a_kb;
                uint32_t addr = base + row * 128 + (kb ^ ((row & 7) * 16));
                ldsm_x4(af[mt], addr);
            }
            uint32_t bfr[2][4];
#pragma unroll
            for (int ng = 0; ng < 2; ng++) {
                int row = wc * 32 + ng * 16 + b_row;
                int kb = kk * 32 + b_kb;
                uint32_t addr = base + TILE_BYTES + row * 128 + (kb ^ ((row & 7) * 16));
                ldsm_x4(bfr[ng], addr);
            }
#pragma unroll
            for (int mt = 0; mt < 4; mt++)
#pragma unroll
                for (int nt = 0; nt < 4; nt++)
                    mma16816(acc[mt][nt], af[mt], &bfr[nt >> 1][(nt & 1) * 2]);
        }

        // ---- fused epilogue: sqrt + row/col partials ----
        float rs[4][2], cs[4][2];
#pragma unroll
        for (int mt = 0; mt < 4; mt++) { rs[mt][0] = 0.f; rs[mt][1] = 0.f; }
#pragma unroll
        for (int nt = 0; nt < 4; nt++) { cs[nt][0] = 0.f; cs[nt][1] = 0.f; }
#pragma unroll
        for (int mt = 0; mt < 4; mt++)
#pragma unroll
            for (int nt = 0; nt < 4; nt++) {
                float s0 = msqrt(acc[mt][nt][0]);
                float s1 = msqrt(acc[mt][nt][1]);
                float s2 = msqrt(acc[mt][nt][2]);
                float s3 = msqrt(acc[mt][nt][3]);
                rs[mt][0] += s0 + s1;
                rs[mt][1] += s2 + s3;
                cs[nt][0] += s0 + s2;
                cs[nt][1] += s1 + s3;
            }

#pragma unroll
        for (int o = 1; o <= 2; o <<= 1)
#pragma unroll
            for (int mt = 0; mt < 4; mt++) {
                rs[mt][0] += __shfl_xor_sync(0xffffffffu, rs[mt][0], o);
                rs[mt][1] += __shfl_xor_sync(0xffffffffu, rs[mt][1], o);
            }
#pragma unroll
        for (int o = 4; o <= 16; o <<= 1)
#pragma unroll
            for (int nt = 0; nt < 4; nt++) {
                cs[nt][0] += __shfl_xor_sync(0xffffffffu, cs[nt][0], o);
                cs[nt][1] += __shfl_xor_sync(0xffffffffu, cs[nt][1], o);
            }

        float* srow = srow2[n & 1];
        float* scol = scol2[n & 1];
        if ((lane & 3) == 0) {
            int g = lane >> 2;  // 0..7
#pragma unroll
            for (int mt = 0; mt < 4; mt++) {
                srow[(wr * 64 + mt * 16 + g) * 4 + wc]     = rs[mt][0];
                srow[(wr * 64 + mt * 16 + g + 8) * 4 + wc] = rs[mt][1];
            }
        }
        if (lane < 4) {
#pragma unroll
            for (int nt = 0; nt < 4; nt++) {
                scol[(wc * 32 + nt * 8 + lane * 2) * 2 + wr]     = cs[nt][0];
                scol[(wc * 32 + nt * 8 + lane * 2 + 1) * 2 + wr] = cs[nt][1];
            }
        }
        __syncthreads();   // all mainloop reads of `buf` complete past this point

        // Producer: grab next ticket, refill this buffer.
        if (tid == 0) {
            int idx2 = (int)atomicAdd(&g_ticket, 1u);
            pending[buf] = idx2;
            if (idx2 < NTILES) {
                int pair2 = idx2 >= NTRI;
                int ti2, tj2;
                tri_decode(idx2 - pair2 * NTRI, ti2, tj2);
                uint32_t dst = smem_base + buf * BUF_BYTES;
                MBAR_EXPECT_TX(mbar0 + 8 * buf, BUF_BYTES);
                bulk_copy(dst, g_Yb[pair2] + ti2 * TILE_BYTES, TILE_BYTES, mbar0 + 8 * buf);
                bulk_copy(dst + TILE_BYTES, g_Yb[pair2] + tj2 * TILE_BYTES, TILE_BYTES, mbar0 + 8 * buf);
            }
        }

        // Coalesced partial writes: g_part[slot][pair*BB + row]
        if (tid < 128) {
            const float4 v = reinterpret_cast<const float4*>(srow)[tid];
            g_part[tj][pair * BB + ti * 128 + tid] = (v.x + v.y) + (v.z + v.w);
        } else if (ti != tj) {
            int c = tid - 128;
            g_part[ti][pair * BB + tj * 128 + c] = scol[c * 2] + scol[c * 2 + 1];
        }

        n++;
        buf++;
        if (buf == NSTAGE) buf = 0;
    }
}

// ---------------------------------------------------------------------------
// Kernel 3: reduce 64 slots per row; 4 threads/row + shuffle combine.
// Also resets the prep grid-barrier counter for the next graph replay.
// ---------------------------------------------------------------------------
__global__ __launch_bounds__(256) void reduce_kernel(float* __restrict__ out) {
    if (blockIdx.x == 0 && threadIdx.x == 0) g_done = 0;
    int idx = blockIdx.x * blockDim.x + threadIdx.x;  // 0..65535
    int row = idx >> 2, q = idx & 3;
    float s0 = 0.f, s1 = 0.f, s2 = 0.f, s3 = 0.f;
    int j0 = q * 16;
#pragma unroll
    for (int j = 0; j < 16; j += 4) {
        s0 += g_part[j0 + j + 0][row];
        s1 += g_part[j0 + j + 1][row];
        s2 += g_part[j0 + j + 2][row];
        s3 += g_part[j0 + j + 3][row];
    }
    float s = (s0 + s1) + (s2 + s3);
    s += __shfl_xor_sync(0xffffffffu, s, 1);
    s += __shfl_xor_sync(0xffffffffu, s, 2);
    if (q == 0) out[row] = s + 8192.0f * 1e-6f;
}

extern "C" void kernel_launch(void* const* d_in, const int* in_sizes, int n_in,
                              void* d_out, int out_size) {
    (void)in_sizes; (void)n_in; (void)out_size;
    const float* anchor   = (const float*)d_in[0];
    const float* positive = (const float*)d_in[1];
    const float* negative = (const float*)d_in[2];
    float* out = (float*)d_out;

    prep_kernel<<<GRID_PREP, 256>>>(anchor, positive, negative);
    cudaFuncSetAttribute(gemm_kernel, cudaFuncAttributeMaxDynamicSharedMemorySize,
                         NSTAGE * BUF_BYTES);
    gemm_kernel<<<GRID_GEMM, 256, NSTAGE * BUF_BYTES>>>();
    reduce_kernel<<<256, 256>>>(out);
}